// round 9
// baseline (speedup 1.0000x reference)
#include <cuda_runtime.h>
#include <cuda_bf16.h>

// ht[b,d] = sum_{s=start}^{start+x-1} hidden[b,s,d]
// start = sum(mask[B-1, :]) - x   (JAX x64-disabled: mask & x are int32)
//
// Fast path (one barrier): speculative window loads rows [S-64, S)
// (load-independent addresses), predicate "x==64 && all mask[B-1,i]==1"
// via one 16B u64x2 pattern-compare per thread, partials staged in smem
// BEFORE the single __syncthreads_and, then the reduction epilogue is
// DISTRIBUTED: warp w reduces columns {2w, 2w+1} with a width-16 shfl tree,
// so no warp serializes a long tail. Slow path: generic (any mask / any x).
//
// Geometry: grid = B * (D4/32) = 256 blocks, 512 threads = 32 float4-cols
// x 16 s-groups. Each warp's loads are one fully-coalesced 512B row slice.

__global__ void __launch_bounds__(512)
srsmlp_window_sum_kernel(const float* __restrict__ hidden,
                         const int* __restrict__ mask,
                         const int* __restrict__ xptr,
                         float* __restrict__ out,
                         int B, int S, int D4, int chunks /* D4/32 */)
{
    const int tid  = threadIdx.x;
    const int col  = tid & 31;        // float4 column within 32-wide chunk
    const int sg   = tid >> 5;        // s-group 0..15 (== warp id)
    const int lane = tid & 31;
    const int b     = blockIdx.x / chunks;
    const int chunk = blockIdx.x - b * chunks;

    const int d4 = (chunk << 5) + col;
    const unsigned rowB = (unsigned)(D4 << 4);        // row stride in bytes

    // ---- speculative window loads: rows [max(S-64,0), ...), no deps ----
    const bool can_spec = (S >= 64);
    const int  gs = can_spec ? (S - 64) : 0;
    const char* sbase = (const char*)hidden
        + ((long long)b * S + gs) * rowB + ((unsigned)d4 << 4);

    float4 v0 = *(const float4*)(sbase + (unsigned)(sg)      * rowB);
    float4 v1 = *(const float4*)(sbase + (unsigned)(sg + 16) * rowB);
    float4 v2 = *(const float4*)(sbase + (unsigned)(sg + 32) * rowB);
    float4 v3 = *(const float4*)(sbase + (unsigned)(sg + 48) * rowB);

    // ---- concurrent scalar + mask predicate (ONE 16B load per thread) ----
    const int x = __ldg(xptr);
    const int* mrow = mask + (long long)(B - 1) * S;
    const int  S4   = S >> 2;                       // 16B chunks
    const ulonglong2* m2 = reinterpret_cast<const ulonglong2*>(mrow);
    const unsigned long long ONES = 0x0000000100000001ULL;

    int okbits = (x == 64) & (int)can_spec & (int)((S & 3) == 0);
    if (S4 == 512) {                  // common case: exactly 1 load/thread
        ulonglong2 m = m2[tid];
        okbits &= (m.x == ONES) & (m.y == ONES);
    } else if ((S & 3) == 0) {
        for (int i = tid; i < S4; i += 512) {
            ulonglong2 m = m2[i];
            okbits &= (m.x == ONES) & (m.y == ONES);
        }
    }

    // ---- combine speculative partials, stage in smem (pre-barrier) ----
    float4 a;
    a.x = (v0.x + v1.x) + (v2.x + v3.x);
    a.y = (v0.y + v1.y) + (v2.y + v3.y);
    a.z = (v0.z + v1.z) + (v2.z + v3.z);
    a.w = (v0.w + v1.w) + (v2.w + v3.w);

    __shared__ float4 red[16][32];    // 8 KB: 16 s-group partials x 32 cols
    red[sg][col] = a;

    // ---- single barrier: sync + block-wide AND of predicate ----
    const int allok = __syncthreads_and(okbits);

    float4* __restrict__ out4 = reinterpret_cast<float4*>(out);

    // distributed epilogue mapping: warp sg handles cols 2*sg + (lane>>4),
    // lane's partial index j = lane & 15.
    const int ecol = (sg << 1) + (lane >> 4);
    const int ej   = lane & 15;

    if (allok) {
        float4 t = red[ej][ecol];
        #pragma unroll
        for (int off = 8; off > 0; off >>= 1) {
            t.x += __shfl_down_sync(0xFFFFFFFFu, t.x, off, 16);
            t.y += __shfl_down_sync(0xFFFFFFFFu, t.y, off, 16);
            t.z += __shfl_down_sync(0xFFFFFFFFu, t.z, off, 16);
            t.w += __shfl_down_sync(0xFFFFFFFFu, t.w, off, 16);
        }
        if (ej == 0)
            out4[(long long)b * D4 + (chunk << 5) + ecol] = t;
        return;
    }

    // ================= slow path (any mask / any x; block-uniform) =========
    __shared__ int s_len;
    if (tid == 0) s_len = 0;
    __syncthreads();
    {
        int macc = 0;
        for (int i = tid; i < S4; i += 512) {
            int4 m = reinterpret_cast<const int4*>(mrow)[i];
            macc += m.x + m.y + m.z + m.w;
        }
        for (int i = (S4 << 2) + tid; i < S; i += 512)
            macc += mrow[i];
        #pragma unroll
        for (int off = 16; off > 0; off >>= 1)
            macc += __shfl_down_sync(0xFFFFFFFFu, macc, off);
        if ((tid & 31) == 0)
            atomicAdd(&s_len, macc);
    }
    __syncthreads();

    const int start = s_len - x;
    float4 acc = make_float4(0.f,0.f,0.f,0.f);
    const char* tbase = (const char*)hidden
        + ((long long)b * S + start) * rowB + ((unsigned)d4 << 4);
    for (int r = sg; r < x; r += 16) {
        float4 v = *(const float4*)(tbase + (unsigned)r * rowB);
        acc.x += v.x; acc.y += v.y; acc.z += v.z; acc.w += v.w;
    }

    __syncthreads();                  // red[] reuse
    red[sg][col] = acc;
    __syncthreads();

    {
        float4 t = red[ej][ecol];
        #pragma unroll
        for (int off = 8; off > 0; off >>= 1) {
            t.x += __shfl_down_sync(0xFFFFFFFFu, t.x, off, 16);
            t.y += __shfl_down_sync(0xFFFFFFFFu, t.y, off, 16);
            t.z += __shfl_down_sync(0xFFFFFFFFu, t.z, off, 16);
            t.w += __shfl_down_sync(0xFFFFFFFFu, t.w, off, 16);
        }
        if (ej == 0)
            out4[(long long)b * D4 + (chunk << 5) + ecol] = t;
    }
}

extern "C" void kernel_launch(void* const* d_in, const int* in_sizes, int n_in,
                              void* d_out, int out_size)
{
    const float* hidden = (const float*)d_in[0];
    const int*   mask   = (const int*)d_in[1];
    const int*   xptr   = (const int*)d_in[2];
    float*       out    = (float*)d_out;

    const long long hidden_elems = in_sizes[0];
    const long long mask_elems   = in_sizes[1];

    const int D  = (int)(hidden_elems / mask_elems);  // 1024
    const int B  = out_size / D;                      // 32
    const int S  = (int)(mask_elems / B);             // 2048
    const int D4 = D >> 2;                            // 256
    const int chunks = D4 >> 5;                       // 8 (32 float4-cols/block)

    dim3 grid(B * chunks);                            // 256 blocks
    srsmlp_window_sum_kernel<<<grid, 512>>>(hidden, mask, xptr, out,
                                            B, S, D4, chunks);
}

// round 10
// speedup vs baseline: 1.2917x; 1.2917x over previous
#include <cuda_runtime.h>
#include <cuda_bf16.h>

// ht[b,d] = sum_{s=start}^{start+x-1} hidden[b,s,d]
// start = sum(mask[B-1, :]) - x   (JAX x64-disabled: mask & x are int32)
//
// Fast path (one barrier): speculative window loads rows [S-64, S)
// (load-independent addresses, 8 per thread -> high MLP), predicate
// "x==64 && all mask[B-1,i]==1" via one 16B u64x2 compare per thread,
// partials staged in smem BEFORE the single __syncthreads_and, epilogue by
// 2 warps with conflict-free lane=col LDS (8-deep). Slow path: generic.
//
// Geometry: grid = B * (D4/64) = 128 blocks, 512 threads = 64 float4-cols
// x 8 s-groups. Each warp's loads are one fully-coalesced 512B row slice.

__global__ void __launch_bounds__(512)
srsmlp_window_sum_kernel(const float* __restrict__ hidden,
                         const int* __restrict__ mask,
                         const int* __restrict__ xptr,
                         float* __restrict__ out,
                         int B, int S, int D4, int chunks /* D4/64 */)
{
    const int tid = threadIdx.x;
    const int col = tid & 63;         // float4 column within 64-wide chunk
    const int sg  = tid >> 6;         // s-group 0..7
    const int b     = blockIdx.x / chunks;
    const int chunk = blockIdx.x - b * chunks;

    const int d4 = (chunk << 6) + col;
    const unsigned rowB = (unsigned)(D4 << 4);        // row stride in bytes

    // ---- speculative window loads: rows [max(S-64,0), ...), no deps ----
    const bool can_spec = (S >= 64);
    const int  gs = can_spec ? (S - 64) : 0;
    const char* sbase = (const char*)hidden
        + ((long long)b * S + gs) * rowB + ((unsigned)d4 << 4);

    float4 v0 = *(const float4*)(sbase + (unsigned)(sg)      * rowB);
    float4 v1 = *(const float4*)(sbase + (unsigned)(sg +  8) * rowB);
    float4 v2 = *(const float4*)(sbase + (unsigned)(sg + 16) * rowB);
    float4 v3 = *(const float4*)(sbase + (unsigned)(sg + 24) * rowB);
    float4 v4 = *(const float4*)(sbase + (unsigned)(sg + 32) * rowB);
    float4 v5 = *(const float4*)(sbase + (unsigned)(sg + 40) * rowB);
    float4 v6 = *(const float4*)(sbase + (unsigned)(sg + 48) * rowB);
    float4 v7 = *(const float4*)(sbase + (unsigned)(sg + 56) * rowB);

    // ---- concurrent scalar + mask predicate (ONE 16B load per thread) ----
    const int x = __ldg(xptr);
    const int* mrow = mask + (long long)(B - 1) * S;
    const int  S4   = S >> 2;                       // 16B chunks
    const ulonglong2* m2 = reinterpret_cast<const ulonglong2*>(mrow);
    const unsigned long long ONES = 0x0000000100000001ULL;

    int okbits = (x == 64) & (int)can_spec & (int)((S & 3) == 0);
    if (S4 == 512) {                  // common case: exactly 1 load/thread
        ulonglong2 m = m2[tid];
        okbits &= (m.x == ONES) & (m.y == ONES);
    } else if ((S & 3) == 0) {
        for (int i = tid; i < S4; i += 512) {
            ulonglong2 m = m2[i];
            okbits &= (m.x == ONES) & (m.y == ONES);
        }
    }

    // ---- combine speculative partials (pairwise), stage in smem ----
    float4 a;
    a.x = ((v0.x + v1.x) + (v2.x + v3.x)) + ((v4.x + v5.x) + (v6.x + v7.x));
    a.y = ((v0.y + v1.y) + (v2.y + v3.y)) + ((v4.y + v5.y) + (v6.y + v7.y));
    a.z = ((v0.z + v1.z) + (v2.z + v3.z)) + ((v4.z + v5.z) + (v6.z + v7.z));
    a.w = ((v0.w + v1.w) + (v2.w + v3.w)) + ((v4.w + v5.w) + (v6.w + v7.w));

    __shared__ float4 red[8][64];     // 8 KB: 8 s-group partials x 64 cols
    red[sg][col] = a;

    // ---- single barrier: sync + block-wide AND of predicate ----
    const int allok = __syncthreads_and(okbits);

    float4* __restrict__ out4 = reinterpret_cast<float4*>(out);

    if (allok) {
        if (tid < 64) {               // warps 0,1 finish; lane=col: no conflicts
            float4 t = red[0][tid];
            #pragma unroll
            for (int j = 1; j < 8; ++j) {
                float4 v = red[j][tid];
                t.x += v.x; t.y += v.y; t.z += v.z; t.w += v.w;
            }
            out4[(long long)b * D4 + (chunk << 6) + tid] = t;
        }
        return;
    }

    // ================= slow path (any mask / any x; block-uniform) =========
    __shared__ int s_len;
    if (tid == 0) s_len = 0;
    __syncthreads();
    {
        int macc = 0;
        for (int i = tid; i < S4; i += 512) {
            int4 m = reinterpret_cast<const int4*>(mrow)[i];
            macc += m.x + m.y + m.z + m.w;
        }
        for (int i = (S4 << 2) + tid; i < S; i += 512)
            macc += mrow[i];
        #pragma unroll
        for (int off = 16; off > 0; off >>= 1)
            macc += __shfl_down_sync(0xFFFFFFFFu, macc, off);
        if ((tid & 31) == 0)
            atomicAdd(&s_len, macc);
    }
    __syncthreads();

    const int start = s_len - x;
    float4 acc = make_float4(0.f,0.f,0.f,0.f);
    const char* tbase = (const char*)hidden
        + ((long long)b * S + start) * rowB + ((unsigned)d4 << 4);
    for (int r = sg; r < x; r += 8) {
        float4 v = *(const float4*)(tbase + (unsigned)r * rowB);
        acc.x += v.x; acc.y += v.y; acc.z += v.z; acc.w += v.w;
    }

    __syncthreads();                  // red[] reuse
    red[sg][col] = acc;
    __syncthreads();

    if (tid < 64) {
        float4 t = red[0][tid];
        #pragma unroll
        for (int j = 1; j < 8; ++j) {
            float4 v = red[j][tid];
            t.x += v.x; t.y += v.y; t.z += v.z; t.w += v.w;
        }
        out4[(long long)b * D4 + (chunk << 6) + tid] = t;
    }
}

extern "C" void kernel_launch(void* const* d_in, const int* in_sizes, int n_in,
                              void* d_out, int out_size)
{
    const float* hidden = (const float*)d_in[0];
    const int*   mask   = (const int*)d_in[1];
    const int*   xptr   = (const int*)d_in[2];
    float*       out    = (float*)d_out;

    const long long hidden_elems = in_sizes[0];
    const long long mask_elems   = in_sizes[1];

    const int D  = (int)(hidden_elems / mask_elems);  // 1024
    const int B  = out_size / D;                      // 32
    const int S  = (int)(mask_elems / B);             // 2048
    const int D4 = D >> 2;                            // 256
    const int chunks = D4 >> 6;                       // 4 (64 float4-cols/block)

    dim3 grid(B * chunks);                            // 128 blocks
    srsmlp_window_sum_kernel<<<grid, 512>>>(hidden, mask, xptr, out,
                                            B, S, D4, chunks);
}

// round 11
// speedup vs baseline: 1.3478x; 1.0435x over previous
#include <cuda_runtime.h>
#include <cuda_bf16.h>

// ht[b,d] = sum_{s=start}^{start+x-1} hidden[b,s,d]
// start = sum(mask[B-1, :]) - x   (JAX x64-disabled: mask & x are int32)
//
// Fast path (one barrier): speculative window loads rows [S-64, S)
// (8 independent loads/thread, load-independent addresses), predicate
// "x==64 && all mask[B-1,i]==1" via two 16B u64x2 compares per thread,
// partials staged in smem BEFORE the single __syncthreads_and, epilogue by
// warp 0 with conflict-free lane=col LDS (8-deep). Slow path: generic.
//
// Geometry: grid = B * (D4/32) = 256 blocks (full-chip spread on 148 SMs),
// 256 threads = 32 float4-cols x 8 s-groups. Each warp's loads are one
// fully-coalesced 512B row slice.

__global__ void __launch_bounds__(256)
srsmlp_window_sum_kernel(const float* __restrict__ hidden,
                         const int* __restrict__ mask,
                         const int* __restrict__ xptr,
                         float* __restrict__ out,
                         int B, int S, int D4, int chunks /* D4/32 */)
{
    const int tid = threadIdx.x;
    const int col = tid & 31;         // float4 column within 32-wide chunk
    const int sg  = tid >> 5;         // s-group 0..7 (== warp id)
    const int b     = blockIdx.x / chunks;
    const int chunk = blockIdx.x - b * chunks;

    const int d4 = (chunk << 5) + col;
    const unsigned rowB = (unsigned)(D4 << 4);        // row stride in bytes

    // ---- speculative window loads: rows [max(S-64,0), ...), no deps ----
    const bool can_spec = (S >= 64);
    const int  gs = can_spec ? (S - 64) : 0;
    const char* sbase = (const char*)hidden
        + ((long long)b * S + gs) * rowB + ((unsigned)d4 << 4);

    float4 v0 = *(const float4*)(sbase + (unsigned)(sg)      * rowB);
    float4 v1 = *(const float4*)(sbase + (unsigned)(sg +  8) * rowB);
    float4 v2 = *(const float4*)(sbase + (unsigned)(sg + 16) * rowB);
    float4 v3 = *(const float4*)(sbase + (unsigned)(sg + 24) * rowB);
    float4 v4 = *(const float4*)(sbase + (unsigned)(sg + 32) * rowB);
    float4 v5 = *(const float4*)(sbase + (unsigned)(sg + 40) * rowB);
    float4 v6 = *(const float4*)(sbase + (unsigned)(sg + 48) * rowB);
    float4 v7 = *(const float4*)(sbase + (unsigned)(sg + 56) * rowB);

    // ---- concurrent scalar + mask predicate (TWO 16B loads per thread) ----
    const int x = __ldg(xptr);
    const int* mrow = mask + (long long)(B - 1) * S;
    const int  S4   = S >> 2;                       // 16B chunks
    const ulonglong2* m2 = reinterpret_cast<const ulonglong2*>(mrow);
    const unsigned long long ONES = 0x0000000100000001ULL;

    int okbits = (x == 64) & (int)can_spec & (int)((S & 3) == 0);
    if (S4 == 512) {                  // common case: exactly 2 loads/thread
        ulonglong2 ma = m2[tid];
        ulonglong2 mb = m2[tid + 256];
        okbits &= (ma.x == ONES) & (ma.y == ONES)
                & (mb.x == ONES) & (mb.y == ONES);
    } else if ((S & 3) == 0) {
        for (int i = tid; i < S4; i += 256) {
            ulonglong2 m = m2[i];
            okbits &= (m.x == ONES) & (m.y == ONES);
        }
    }

    // ---- combine speculative partials (pairwise), stage in smem ----
    float4 a;
    a.x = ((v0.x + v1.x) + (v2.x + v3.x)) + ((v4.x + v5.x) + (v6.x + v7.x));
    a.y = ((v0.y + v1.y) + (v2.y + v3.y)) + ((v4.y + v5.y) + (v6.y + v7.y));
    a.z = ((v0.z + v1.z) + (v2.z + v3.z)) + ((v4.z + v5.z) + (v6.z + v7.z));
    a.w = ((v0.w + v1.w) + (v2.w + v3.w)) + ((v4.w + v5.w) + (v6.w + v7.w));

    __shared__ float4 red[8][32];     // 4 KB: 8 s-group partials x 32 cols
    red[sg][col] = a;

    // ---- single barrier: sync + block-wide AND of predicate ----
    const int allok = __syncthreads_and(okbits);

    float4* __restrict__ out4 = reinterpret_cast<float4*>(out);

    if (allok) {
        if (tid < 32) {               // warp 0 finishes; lane=col: conflict-free
            float4 t = red[0][tid];
            #pragma unroll
            for (int j = 1; j < 8; ++j) {
                float4 v = red[j][tid];
                t.x += v.x; t.y += v.y; t.z += v.z; t.w += v.w;
            }
            out4[(long long)b * D4 + (chunk << 5) + tid] = t;
        }
        return;
    }

    // ================= slow path (any mask / any x; block-uniform) =========
    __shared__ int s_len;
    if (tid == 0) s_len = 0;
    __syncthreads();
    {
        int macc = 0;
        for (int i = tid; i < S4; i += 256) {
            int4 m = reinterpret_cast<const int4*>(mrow)[i];
            macc += m.x + m.y + m.z + m.w;
        }
        for (int i = (S4 << 2) + tid; i < S; i += 256)
            macc += mrow[i];
        #pragma unroll
        for (int off = 16; off > 0; off >>= 1)
            macc += __shfl_down_sync(0xFFFFFFFFu, macc, off);
        if ((tid & 31) == 0)
            atomicAdd(&s_len, macc);
    }
    __syncthreads();

    const int start = s_len - x;
    float4 acc = make_float4(0.f,0.f,0.f,0.f);
    const char* tbase = (const char*)hidden
        + ((long long)b * S + start) * rowB + ((unsigned)d4 << 4);
    for (int r = sg; r < x; r += 8) {
        float4 v = *(const float4*)(tbase + (unsigned)r * rowB);
        acc.x += v.x; acc.y += v.y; acc.z += v.z; acc.w += v.w;
    }

    __syncthreads();                  // red[] reuse
    red[sg][col] = acc;
    __syncthreads();

    if (tid < 32) {
        float4 t = red[0][tid];
        #pragma unroll
        for (int j = 1; j < 8; ++j) {
            float4 v = red[j][tid];
            t.x += v.x; t.y += v.y; t.z += v.z; t.w += v.w;
        }
        out4[(long long)b * D4 + (chunk << 5) + tid] = t;
    }
}

extern "C" void kernel_launch(void* const* d_in, const int* in_sizes, int n_in,
                              void* d_out, int out_size)
{
    const float* hidden = (const float*)d_in[0];
    const int*   mask   = (const int*)d_in[1];
    const int*   xptr   = (const int*)d_in[2];
    float*       out    = (float*)d_out;

    const long long hidden_elems = in_sizes[0];
    const long long mask_elems   = in_sizes[1];

    const int D  = (int)(hidden_elems / mask_elems);  // 1024
    const int B  = out_size / D;                      // 32
    const int S  = (int)(mask_elems / B);             // 2048
    const int D4 = D >> 2;                            // 256
    const int chunks = D4 >> 5;                       // 8 (32 float4-cols/block)

    dim3 grid(B * chunks);                            // 256 blocks
    srsmlp_window_sum_kernel<<<grid, 256>>>(hidden, mask, xptr, out,
                                            B, S, D4, chunks);
}